// round 8
// baseline (speedup 1.0000x reference)
#include <cuda_runtime.h>
#include <cuda_bf16.h>
#include <cfloat>
#include <cstdint>

// ---------------------------------------------------------------------------
// Problem constants
// ---------------------------------------------------------------------------
#define NTEST   16384
#define NTRAIN  16384
#define DIM     192
#define NCLASS  2
#define KNN     5

#define TM      128                 // test rows per CTA
#define TN      128                 // train cols per tile
#define NTILES  (NTRAIN / TN)       // 128
#define KSTEPS  (DIM / 16)          // 12 mma k-steps
#define NTHREADS 256                // 8 warps: 4 (M) x 2 (N), warp tile 32x64
#define NSLOT   5                   // private top-5 per (thread,row-slot)
#define NCANDR  40                  // 8 owners x 5 candidates per row

#define ROWSTRIDE 200               // bf16 elems per smem row (400B: conflict-free ldmatrix)

// ---------------------------------------------------------------------------
// Global scratch (no cudaMalloc allowed)
// ---------------------------------------------------------------------------
__device__ float         g_ynorm[NTRAIN];
__device__ __nv_bfloat16 g_Abf[NTEST * DIM];
__device__ __nv_bfloat16 g_Bbf[NTRAIN * DIM];

// ---------------------------------------------------------------------------
// PTX helpers (base ISA, legal on sm_100)
// ---------------------------------------------------------------------------
__device__ __forceinline__ uint32_t smem_u32(const void* p) {
    uint32_t a;
    asm("{ .reg .u64 t; cvta.to.shared.u64 t, %1; cvt.u32.u64 %0, t; }"
        : "=r"(a) : "l"(p));
    return a;
}

#define CP_ASYNC16(dst, src) \
    asm volatile("cp.async.cg.shared.global [%0], [%1], 16;" :: "r"(dst), "l"(src))
#define CP_COMMIT() asm volatile("cp.async.commit_group;" ::: "memory")
#define CP_WAIT0()  asm volatile("cp.async.wait_group 0;" ::: "memory")
#define CP_WAIT1()  asm volatile("cp.async.wait_group 1;" ::: "memory")

#define LDMATRIX_X4(r0, r1, r2, r3, addr) \
    asm volatile("ldmatrix.sync.aligned.m8n8.x4.shared.b16 {%0,%1,%2,%3}, [%4];" \
                 : "=r"(r0), "=r"(r1), "=r"(r2), "=r"(r3) : "r"(addr))

__device__ __forceinline__ void mma_bf16(float* c,
                                         uint32_t a0, uint32_t a1, uint32_t a2, uint32_t a3,
                                         uint32_t b0, uint32_t b1) {
    asm volatile("mma.sync.aligned.m16n8k16.row.col.f32.bf16.bf16.f32 "
                 "{%0,%1,%2,%3}, {%4,%5,%6,%7}, {%8,%9}, {%0,%1,%2,%3};"
                 : "+f"(c[0]), "+f"(c[1]), "+f"(c[2]), "+f"(c[3])
                 : "r"(a0), "r"(a1), "r"(a2), "r"(a3), "r"(b0), "r"(b1));
}

// ---------------------------------------------------------------------------
// SMEM layout (bytes). A staging overlaps the candidate-dump area:
// A is consumed into registers in the prologue; cand used only at the end.
// ---------------------------------------------------------------------------
#define TILE_BYTES   (TM * ROWSTRIDE * 2)    // 51200
#define OFF_B        0                       // two buffers: +0 / +51200
#define OFF_YNS      102400                  // float [2][128]
#define OFF_CAND     103424                  // int [128][NCANDR] = 20480 B
#define OFF_A        103424                  // A staging (51200 B) overlaps cand
#define SMEM_BYTES   154624

// load a 128x192 bf16 tile into padded smem via cp.async (24 x 16B per row)
__device__ __forceinline__ void tile_load_async(uint32_t sdst, const __nv_bfloat16* src,
                                                int tid) {
    #pragma unroll
    for (int it = 0; it < 12; it++) {
        int g  = tid + it * NTHREADS;        // 0..3071
        int r  = g / 24;
        int ch = g % 24;
        uint32_t dst = sdst + r * (ROWSTRIDE * 2) + ch * 16;
        const char* s = (const char*)(src + (size_t)r * DIM) + ch * 16;
        CP_ASYNC16(dst, s);
    }
}

// private sorted-ascending top-5 insert (lists live in local mem; thr in reg)
__device__ __forceinline__ void insert5(float* cd, int* ci, float& thr,
                                        float d, int col) {
    if (d < thr) {
        int j = NSLOT - 1;
        while (j > 0 && cd[j - 1] > d) {
            cd[j] = cd[j - 1]; ci[j] = ci[j - 1]; j--;
        }
        cd[j] = d; ci[j] = col;
        thr = cd[NSLOT - 1];
    }
}

// ---------------------------------------------------------------------------
// Prep kernels
// ---------------------------------------------------------------------------
__global__ void ynorm_kernel(const float* __restrict__ Htrain) {
    int gwarp = (blockIdx.x * blockDim.x + threadIdx.x) >> 5;
    int lane  = threadIdx.x & 31;
    if (gwarp >= NTRAIN) return;
    const float* row = Htrain + (size_t)gwarp * DIM;
    float s = 0.f;
    #pragma unroll
    for (int k = lane; k < DIM; k += 32) { float v = row[k]; s += v * v; }
    #pragma unroll
    for (int o = 16; o; o >>= 1) s += __shfl_xor_sync(0xffffffffu, s, o);
    if (lane == 0) g_ynorm[gwarp] = s;
}

__global__ void convert_kernel(const float* __restrict__ Htest,
                               const float* __restrict__ Htrain) {
    int total = NTEST * DIM / 2;
    for (int i = blockIdx.x * blockDim.x + threadIdx.x; i < total;
         i += gridDim.x * blockDim.x) {
        float2 a = ((const float2*)Htest)[i];
        float2 b = ((const float2*)Htrain)[i];
        ((__nv_bfloat162*)g_Abf)[i] = __floats2bfloat162_rn(a.x, a.y);
        ((__nv_bfloat162*)g_Bbf)[i] = __floats2bfloat162_rn(b.x, b.y);
    }
}

// ---------------------------------------------------------------------------
// Main kernel: bf16 mma.sync GEMM (A in regs) -> PRIVATE top-5/slot -> fp32 re-rank
// ---------------------------------------------------------------------------
__global__ __launch_bounds__(NTHREADS, 1)
void knn_mma_kernel(const float* __restrict__ Htest,
                    const float* __restrict__ Htrain,
                    const float* __restrict__ phat,
                    float* __restrict__ out) {
    extern __shared__ __align__(1024) char smem[];
    const uint32_t sbase = smem_u32(smem);
    const int tid   = threadIdx.x;
    const int wid   = tid >> 5;
    const int lid   = tid & 31;
    const int warpM = wid & 3;       // 0..3 -> rows warpM*32..+31
    const int warpN = wid >> 2;      // 0..1 -> cols warpN*64..+63
    const int m0    = blockIdx.x * TM;

    float* yns  = (float*)(smem + OFF_YNS);
    int*   cand = (int*)  (smem + OFF_CAND);

    // ---- prologue: stage A + B0 via cp.async ----
    tile_load_async(sbase + OFF_A, g_Abf + (size_t)m0 * DIM, tid);
    tile_load_async(sbase + OFF_B, g_Bbf, tid);
    CP_COMMIT();
    CP_WAIT0();
    __syncthreads();

    // ---- load A fragments into registers ONCE ----
    const int lrow   = lid & 15;
    const int lchunk = lid >> 4;
    uint32_t afrag[2][KSTEPS][4];
    #pragma unroll
    for (int mf = 0; mf < 2; mf++) {
        uint32_t base = sbase + OFF_A +
                        (warpM * 32 + mf * 16 + lrow) * (ROWSTRIDE * 2) + lchunk * 16;
        #pragma unroll
        for (int ks = 0; ks < KSTEPS; ks++)
            LDMATRIX_X4(afrag[mf][ks][0], afrag[mf][ks][1],
                        afrag[mf][ks][2], afrag[mf][ks][3], base + ks * 32);
    }
    __syncthreads();   // A staging dead; cand area free for reuse at the end

    const int erow0 = warpM * 32 + (lid >> 2);
    const int ecol0 = warpN * 64 + 2 * (lid & 3);

    // ---- private selection state: 4 row-slots, top-5 each ----
    float cd[4][NSLOT];
    int   ci[4][NSLOT];
    float thrS[4];
    #pragma unroll
    for (int s = 0; s < 4; s++) {
        thrS[s] = FLT_MAX;
        #pragma unroll
        for (int i = 0; i < NSLOT; i++) { cd[s][i] = FLT_MAX; ci[s][i] = -1; }
    }

    // ---- main loop over B tiles (2 syncs per tile) ----
    for (int jt = 0; jt < NTILES; jt++) {
        const int cur = jt & 1;

        if (jt + 1 < NTILES)
            tile_load_async(sbase + OFF_B + (1 - cur) * TILE_BYTES,
                            g_Bbf + (size_t)(jt + 1) * TN * DIM, tid);
        CP_COMMIT();
        if (tid < TM) yns[cur * TM + tid] = g_ynorm[jt * TN + tid];
        CP_WAIT1();          // current B tile resident
        __syncthreads();

        // ---- 128x128x192: B from smem, A from registers ----
        float acc[2][8][4];
        #pragma unroll
        for (int mf = 0; mf < 2; mf++)
            #pragma unroll
            for (int nf = 0; nf < 8; nf++)
                #pragma unroll
                for (int q = 0; q < 4; q++) acc[mf][nf][q] = 0.f;

        uint32_t b_base = sbase + OFF_B + cur * TILE_BYTES +
                          (warpN * 64 + lrow) * (ROWSTRIDE * 2) + lchunk * 16;

        #pragma unroll
        for (int ks = 0; ks < KSTEPS; ks++) {
            const uint32_t ka = ks * 32;
            uint32_t b[4][4];
            #pragma unroll
            for (int g = 0; g < 4; g++)
                LDMATRIX_X4(b[g][0], b[g][1], b[g][2], b[g][3],
                            b_base + g * 16 * (ROWSTRIDE * 2) + ka);
            #pragma unroll
            for (int mf = 0; mf < 2; mf++)
                #pragma unroll
                for (int nf = 0; nf < 8; nf++)
                    mma_bf16(acc[mf][nf],
                             afrag[mf][ks][0], afrag[mf][ks][1],
                             afrag[mf][ks][2], afrag[mf][ks][3],
                             b[nf >> 1][nf & 1], b[nf >> 1][2 + (nf & 1)]);
        }

        // ---- epilogue: fully private (no atomics, no extra barriers) ----
        const float* yn = yns + cur * TM;
        const int colbase = jt * TN;
        #pragma unroll
        for (int nf = 0; nf < 8; nf++) {
            const int col0 = ecol0 + nf * 8;
            const int col1 = col0 + 1;
            const float y0 = yn[col0];
            const float y1 = yn[col1];
            const int g0 = colbase + col0;
            const int g1 = colbase + col1;
            #pragma unroll
            for (int mf = 0; mf < 2; mf++) {
                const float* cc = acc[mf][nf];
                insert5(cd[mf*2+0], ci[mf*2+0], thrS[mf*2+0], fmaf(-2.f, cc[0], y0), g0);
                insert5(cd[mf*2+0], ci[mf*2+0], thrS[mf*2+0], fmaf(-2.f, cc[1], y1), g1);
                insert5(cd[mf*2+1], ci[mf*2+1], thrS[mf*2+1], fmaf(-2.f, cc[2], y0), g0);
                insert5(cd[mf*2+1], ci[mf*2+1], thrS[mf*2+1], fmaf(-2.f, cc[3], y1), g1);
            }
        }
        __syncthreads();     // all reads of buf[cur] done before jt+1 overwrites it
    }

    // ---- dump 8x5 candidates per row to smem ----
    const int tslot = (warpN * 4 + (lid & 3)) * NSLOT;
    #pragma unroll
    for (int s = 0; s < 4; s++) {
        const int mf = s >> 1, half = s & 1;
        const int row = warpM * 32 + mf * 16 + (lid >> 2) + half * 8;
        #pragma unroll
        for (int i = 0; i < NSLOT; i++)
            cand[row * NCANDR + tslot + i] = ci[s][i];
    }
    __syncthreads();

    // ---- exact fp32 re-rank: warp per row, 40 candidates ----
    for (int r = wid; r < TM; r += 8) {
        const int rowg = m0 + r;
        const float* xrow = Htest + (size_t)rowg * DIM;
        float xv[6];
        #pragma unroll
        for (int j = 0; j < 6; j++) xv[j] = xrow[lid + 32 * j];

        float bd[KNN]; int bi[KNN];
        #pragma unroll
        for (int i = 0; i < KNN; i++) { bd[i] = FLT_MAX; bi[i] = 0x7fffffff; }

        for (int c = 0; c < NCANDR; c++) {
            int idx = cand[r * NCANDR + c];
            if (idx < 0) continue;
            const float* trow = Htrain + (size_t)idx * DIM;
            float s = 0.f;
            #pragma unroll
            for (int j = 0; j < 6; j++) s = fmaf(xv[j], trow[lid + 32 * j], s);
            #pragma unroll
            for (int o = 16; o; o >>= 1) s += __shfl_xor_sync(0xffffffffu, s, o);
            if (lid == 0) {
                float d = g_ynorm[idx] - 2.0f * s;
                int j = KNN;
                while (j > 0 && (d < bd[j - 1] ||
                                 (d == bd[j - 1] && idx < bi[j - 1]))) j--;
                if (j < KNN) {
                    for (int q = KNN - 1; q > j; q--) { bd[q] = bd[q-1]; bi[q] = bi[q-1]; }
                    bd[j] = d; bi[j] = idx;
                }
            }
        }
        if (lid == 0) {
            float s0 = 0.f, s1 = 0.f;
            #pragma unroll
            for (int i = 0; i < KNN; i++) {
                int idx = bi[i];
                s0 += phat[idx];
                s1 += phat[NTRAIN + idx];
            }
            out[rowg]         = s0 * (1.0f / KNN);
            out[NTEST + rowg] = s1 * (1.0f / KNN);
        }
    }
}

// ---------------------------------------------------------------------------
extern "C" void kernel_launch(void* const* d_in, const int* in_sizes, int n_in,
                              void* d_out, int out_size) {
    const float* Htest  = (const float*)d_in[0];
    const float* Htrain = (const float*)d_in[1];
    const float* phat   = (const float*)d_in[2];
    float* out = (float*)d_out;

    {
        int threads = 256;
        int blocks  = (NTRAIN * 32 + threads - 1) / threads;
        ynorm_kernel<<<blocks, threads>>>(Htrain);
    }
    convert_kernel<<<1024, 256>>>(Htest, Htrain);

    cudaFuncSetAttribute(knn_mma_kernel,
                         cudaFuncAttributeMaxDynamicSharedMemorySize, SMEM_BYTES);
    knn_mma_kernel<<<NTEST / TM, NTHREADS, SMEM_BYTES>>>(Htest, Htrain, phat, out);
}

// round 9
// speedup vs baseline: 1.5564x; 1.5564x over previous
#include <cuda_runtime.h>
#include <cuda_bf16.h>
#include <cfloat>
#include <cstdint>

// ---------------------------------------------------------------------------
// Problem constants
// ---------------------------------------------------------------------------
#define NTEST   16384
#define NTRAIN  16384
#define DIM     192
#define NCLASS  2
#define KNN     5

#define TM      128                 // test rows per CTA
#define TN      128                 // train cols per tile
#define NTILES  (NTRAIN / TN)       // 128
#define KSTEPS  (DIM / 16)          // 12 mma k-steps
#define NTHREADS 512                // 16 warps: 4 (M) x 4 (N), warp tile 32x32
#define NCAND   16                  // top-16 kept per row (in compact-thread regs)
#define NCAP    64                  // buffer depth == max inserts per 64-col phase

#define ROWSTRIDE 200               // bf16 elems per smem row (400B: conflict-free ldmatrix)

// ---------------------------------------------------------------------------
// Global scratch (no cudaMalloc allowed)
// ---------------------------------------------------------------------------
__device__ float         g_ynorm[NTRAIN];
__device__ __nv_bfloat16 g_Abf[NTEST * DIM];
__device__ __nv_bfloat16 g_Bbf[NTRAIN * DIM];

// ---------------------------------------------------------------------------
// PTX helpers (base ISA, legal on sm_100)
// ---------------------------------------------------------------------------
__device__ __forceinline__ uint32_t smem_u32(const void* p) {
    uint32_t a;
    asm("{ .reg .u64 t; cvta.to.shared.u64 t, %1; cvt.u32.u64 %0, t; }"
        : "=r"(a) : "l"(p));
    return a;
}

#define CP_ASYNC16(dst, src) \
    asm volatile("cp.async.cg.shared.global [%0], [%1], 16;" :: "r"(dst), "l"(src))
#define CP_COMMIT() asm volatile("cp.async.commit_group;" ::: "memory")
#define CP_WAIT0()  asm volatile("cp.async.wait_group 0;" ::: "memory")
#define CP_WAIT1()  asm volatile("cp.async.wait_group 1;" ::: "memory")

#define LDMATRIX_X4(r0, r1, r2, r3, addr) \
    asm volatile("ldmatrix.sync.aligned.m8n8.x4.shared.b16 {%0,%1,%2,%3}, [%4];" \
                 : "=r"(r0), "=r"(r1), "=r"(r2), "=r"(r3) : "r"(addr))

__device__ __forceinline__ void mma_bf16(float* c,
                                         uint32_t a0, uint32_t a1, uint32_t a2, uint32_t a3,
                                         uint32_t b0, uint32_t b1) {
    asm volatile("mma.sync.aligned.m16n8k16.row.col.f32.bf16.bf16.f32 "
                 "{%0,%1,%2,%3}, {%4,%5,%6,%7}, {%8,%9}, {%0,%1,%2,%3};"
                 : "+f"(c[0]), "+f"(c[1]), "+f"(c[2]), "+f"(c[3])
                 : "r"(a0), "r"(a1), "r"(a2), "r"(a3), "r"(b0), "r"(b1));
}

// ---------------------------------------------------------------------------
// SMEM layout (bytes)
// ---------------------------------------------------------------------------
#define TILE_BYTES   (TM * ROWSTRIDE * 2)    // 51200
#define OFF_B        0                       // double buffer: +0 / +51200
#define OFF_A        102400                  // single A buffer (live all kernel)
#define OFF_YNS      153600                  // float [128]
#define OFF_THR      154112                  // float [128]
#define OFF_CNT      154624                  // int   [128]
#define OFF_BUFD     155136                  // float [128][NCAP] (32768)
#define OFF_BUFI     187904                  // int   [128][NCAP] (32768) / cand reuse
#define SMEM_BYTES   220672

// load a 128x192 bf16 tile into padded smem via cp.async (24 x 16B per row)
__device__ __forceinline__ void tile_load_async(uint32_t sdst, const __nv_bfloat16* src,
                                                int tid) {
    #pragma unroll
    for (int it = 0; it < (TM * 24) / NTHREADS; it++) {
        int g  = tid + it * NTHREADS;        // 0..3071
        int r  = g / 24;
        int ch = g % 24;
        uint32_t dst = sdst + r * (ROWSTRIDE * 2) + ch * 16;
        const char* s = (const char*)(src + (size_t)r * DIM) + ch * 16;
        CP_ASYNC16(dst, s);
    }
}

// ---------------------------------------------------------------------------
// Fused prep kernel: one warp handles one row index w (< NTRAIN):
//   - convert Htrain[w] -> g_Bbf[w] and accumulate its squared norm -> g_ynorm[w]
//   - convert Htest[w]  -> g_Abf[w]
// ---------------------------------------------------------------------------
__global__ void prep_kernel(const float* __restrict__ Htest,
                            const float* __restrict__ Htrain) {
    int w    = (blockIdx.x * blockDim.x + threadIdx.x) >> 5;
    int lane = threadIdx.x & 31;
    if (w >= NTRAIN) return;

    const float2* tr = (const float2*)(Htrain + (size_t)w * DIM);
    const float2* te = (const float2*)(Htest  + (size_t)w * DIM);
    __nv_bfloat162* ob = (__nv_bfloat162*)(g_Bbf + (size_t)w * DIM);
    __nv_bfloat162* oa = (__nv_bfloat162*)(g_Abf + (size_t)w * DIM);

    float s = 0.f;
    #pragma unroll
    for (int j = 0; j < 3; j++) {
        int i = lane + 32 * j;               // 96 float2 per row
        float2 b = tr[i];
        float2 a = te[i];
        s = fmaf(b.x, b.x, s);
        s = fmaf(b.y, b.y, s);
        ob[i] = __floats2bfloat162_rn(b.x, b.y);
        oa[i] = __floats2bfloat162_rn(a.x, a.y);
    }
    #pragma unroll
    for (int o = 16; o; o >>= 1) s += __shfl_xor_sync(0xffffffffu, s, o);
    if (lane == 0) g_ynorm[w] = s;
}

// ---------------------------------------------------------------------------
// Main kernel: 16-warp bf16 mma.sync GEMM -> shared-atomic top-16 -> fp32 re-rank
// ---------------------------------------------------------------------------
__global__ __launch_bounds__(NTHREADS, 1)
void knn_mma_kernel(const float* __restrict__ Htest,
                    const float* __restrict__ Htrain,
                    const float* __restrict__ phat,
                    float* __restrict__ out) {
    extern __shared__ __align__(1024) char smem[];
    const uint32_t sbase = smem_u32(smem);
    const int tid   = threadIdx.x;
    const int wid   = tid >> 5;
    const int lid   = tid & 31;
    const int warpM = wid & 3;       // 0..3 -> rows warpM*32..+31
    const int warpN = wid >> 2;      // 0..3 -> cols warpN*32..+31
    const int m0    = blockIdx.x * TM;

    float* yns  = (float*)(smem + OFF_YNS);
    float* thr  = (float*)(smem + OFF_THR);
    int*   cnt  = (int*)  (smem + OFF_CNT);
    float* bufd = (float*)(smem + OFF_BUFD);
    int*   bufi = (int*)  (smem + OFF_BUFI);

    // ---- prologue: A tile + B tile 0 ----
    tile_load_async(sbase + OFF_A, g_Abf + (size_t)m0 * DIM, tid);
    tile_load_async(sbase + OFF_B, g_Bbf, tid);
    CP_COMMIT();

    if (tid < TM) { thr[tid] = FLT_MAX; cnt[tid] = 0; }

    // private top-16 for the compact thread (row == tid, tid < 128)
    float pd[NCAND]; int pi[NCAND];
    #pragma unroll
    for (int i = 0; i < NCAND; i++) { pd[i] = FLT_MAX; pi[i] = -1; }

    CP_WAIT0();
    __syncthreads();

    const int lrow   = lid & 15;
    const int lchunk = lid >> 4;
    uint32_t a_addr[2];
    #pragma unroll
    for (int mf = 0; mf < 2; mf++)
        a_addr[mf] = sbase + OFF_A +
                     (warpM * 32 + mf * 16 + lrow) * (ROWSTRIDE * 2) + lchunk * 16;

    const int erow0 = warpM * 32 + (lid >> 2);
    const int ecol0 = warpN * 32 + 2 * (lid & 3);

    // ---- main loop over B tiles ----
    for (int jt = 0; jt < NTILES; jt++) {
        const int cur = jt & 1;

        if (jt + 1 < NTILES)
            tile_load_async(sbase + OFF_B + (1 - cur) * TILE_BYTES,
                            g_Bbf + (size_t)(jt + 1) * TN * DIM, tid);
        CP_COMMIT();
        if (tid < TM) yns[tid] = g_ynorm[jt * TN + tid];   // safe: barrier below,
        CP_WAIT1();                                        // prev tile fully done
        __syncthreads();

        // ---- 128x128x192 bf16 mma: warp tile 32x32 ----
        float acc[2][4][4];
        #pragma unroll
        for (int mf = 0; mf < 2; mf++)
            #pragma unroll
            for (int nf = 0; nf < 4; nf++)
                #pragma unroll
                for (int q = 0; q < 4; q++) acc[mf][nf][q] = 0.f;

        uint32_t b_base = sbase + OFF_B + cur * TILE_BYTES +
                          (warpN * 32 + lrow) * (ROWSTRIDE * 2) + lchunk * 16;

        #pragma unroll
        for (int ks = 0; ks < KSTEPS; ks++) {
            const uint32_t ka = ks * 32;
            uint32_t a[2][4], b[2][4];
            LDMATRIX_X4(a[0][0], a[0][1], a[0][2], a[0][3], a_addr[0] + ka);
            LDMATRIX_X4(a[1][0], a[1][1], a[1][2], a[1][3], a_addr[1] + ka);
            LDMATRIX_X4(b[0][0], b[0][1], b[0][2], b[0][3], b_base + ka);
            LDMATRIX_X4(b[1][0], b[1][1], b[1][2], b[1][3],
                        b_base + 16 * (ROWSTRIDE * 2) + ka);
            #pragma unroll
            for (int mf = 0; mf < 2; mf++)
                #pragma unroll
                for (int nf = 0; nf < 4; nf++)
                    mma_bf16(acc[mf][nf],
                             a[mf][0], a[mf][1], a[mf][2], a[mf][3],
                             b[nf >> 1][nf & 1], b[nf >> 1][2 + (nf & 1)]);
        }

        // ---- epilogue: 2 phases x 64 cols/row; inserts <= NCAP by construction ----
        const int colbase = jt * TN;
        #pragma unroll
        for (int ph = 0; ph < 2; ph++) {
            #pragma unroll
            for (int nfp = 0; nfp < 2; nfp++) {
                const int nf   = ph * 2 + nfp;
                const int col0 = ecol0 + nf * 8;
                const int col1 = col0 + 1;
                const float y0 = yns[col0];
                const float y1 = yns[col1];
                const int g0 = colbase + col0;
                const int g1 = colbase + col1;
                #pragma unroll
                for (int mf = 0; mf < 2; mf++) {
                    const float* cc = acc[mf][nf];
                    const int r0 = erow0 + mf * 16;
                    const int r1 = r0 + 8;
                    float d00 = fmaf(-2.f, cc[0], y0);
                    float d01 = fmaf(-2.f, cc[1], y1);
                    float d10 = fmaf(-2.f, cc[2], y0);
                    float d11 = fmaf(-2.f, cc[3], y1);
                    if (d00 < thr[r0]) {
                        int p = atomicAdd(&cnt[r0], 1);
                        bufd[r0*NCAP+p] = d00; bufi[r0*NCAP+p] = g0;
                    }
                    if (d01 < thr[r0]) {
                        int p = atomicAdd(&cnt[r0], 1);
                        bufd[r0*NCAP+p] = d01; bufi[r0*NCAP+p] = g1;
                    }
                    if (d10 < thr[r1]) {
                        int p = atomicAdd(&cnt[r1], 1);
                        bufd[r1*NCAP+p] = d10; bufi[r1*NCAP+p] = g0;
                    }
                    if (d11 < thr[r1]) {
                        int p = atomicAdd(&cnt[r1], 1);
                        bufd[r1*NCAP+p] = d11; bufi[r1*NCAP+p] = g1;
                    }
                }
            }
            __syncthreads();
            if (tid < TM) {
                int cn = cnt[tid];
                if (cn > 0) {
                    for (int i = 0; i < cn; i++) {
                        float d = bufd[tid * NCAP + i];
                        if (d < pd[NCAND - 1]) {
                            int idx = bufi[tid * NCAP + i];
                            int j = NCAND - 1;
                            while (j > 0 && pd[j - 1] > d) {
                                pd[j] = pd[j - 1]; pi[j] = pi[j - 1]; j--;
                            }
                            pd[j] = d; pi[j] = idx;
                        }
                    }
                    thr[tid] = pd[NCAND - 1];
                    cnt[tid] = 0;
                }
            }
            __syncthreads();
        }
    }

    // ---- dump candidates (reuse bufi region) ----
    int* cand = bufi;                          // [128][NCAND]
    if (tid < TM) {
        #pragma unroll
        for (int i = 0; i < NCAND; i++) cand[tid * NCAND + i] = pi[i];
    }
    __syncthreads();

    // ---- exact fp32 re-rank: warp per row, 16 candidates ----
    for (int r = wid; r < TM; r += 16) {
        const int rowg = m0 + r;
        const float* xrow = Htest + (size_t)rowg * DIM;
        float xv[6];
        #pragma unroll
        for (int j = 0; j < 6; j++) xv[j] = xrow[lid + 32 * j];

        float bd[KNN]; int bi[KNN];
        #pragma unroll
        for (int i = 0; i < KNN; i++) { bd[i] = FLT_MAX; bi[i] = 0x7fffffff; }

        for (int c = 0; c < NCAND; c++) {
            int idx = cand[r * NCAND + c];
            if (idx < 0) continue;
            const float* trow = Htrain + (size_t)idx * DIM;
            float s = 0.f;
            #pragma unroll
            for (int j = 0; j < 6; j++) s = fmaf(xv[j], trow[lid + 32 * j], s);
            #pragma unroll
            for (int o = 16; o; o >>= 1) s += __shfl_xor_sync(0xffffffffu, s, o);
            if (lid == 0) {
                float d = g_ynorm[idx] - 2.0f * s;
                int j = KNN;
                while (j > 0 && (d < bd[j - 1] ||
                                 (d == bd[j - 1] && idx < bi[j - 1]))) j--;
                if (j < KNN) {
                    for (int q = KNN - 1; q > j; q--) { bd[q] = bd[q-1]; bi[q] = bi[q-1]; }
                    bd[j] = d; bi[j] = idx;
                }
            }
        }
        if (lid == 0) {
            float s0 = 0.f, s1 = 0.f;
            #pragma unroll
            for (int i = 0; i < KNN; i++) {
                int idx = bi[i];
                s0 += phat[idx];
                s1 += phat[NTRAIN + idx];
            }
            out[rowg]         = s0 * (1.0f / KNN);
            out[NTEST + rowg] = s1 * (1.0f / KNN);
        }
    }
}

// ---------------------------------------------------------------------------
extern "C" void kernel_launch(void* const* d_in, const int* in_sizes, int n_in,
                              void* d_out, int out_size) {
    const float* Htest  = (const float*)d_in[0];
    const float* Htrain = (const float*)d_in[1];
    const float* phat   = (const float*)d_in[2];
    float* out = (float*)d_out;

    // fused prep: 1 warp per row index (convert A+B, ynorm)
    prep_kernel<<<(NTRAIN * 32) / 256, 256>>>(Htest, Htrain);

    cudaFuncSetAttribute(knn_mma_kernel,
                         cudaFuncAttributeMaxDynamicSharedMemorySize, SMEM_BYTES);
    knn_mma_kernel<<<NTEST / TM, NTHREADS, SMEM_BYTES>>>(Htest, Htrain, phat, out);
}

// round 10
// speedup vs baseline: 1.7226x; 1.1068x over previous
#include <cuda_runtime.h>
#include <cuda_bf16.h>
#include <cuda_fp8.h>
#include <cfloat>
#include <cstdint>

// ---------------------------------------------------------------------------
// Problem constants
// ---------------------------------------------------------------------------
#define NTEST   16384
#define NTRAIN  16384
#define DIM     192
#define NCLASS  2
#define KNN     5

#define TM      128                 // test rows per CTA
#define TN      128                 // train cols per tile
#define NTILES  (NTRAIN / TN)       // 128
#define KSTEPS  (DIM / 32)          // 6 mma k-steps (fp8: K=32 per step)
#define NTHREADS 512                // 16 warps: 4 (M) x 4 (N), warp tile 32x32
#define NCAND   16                  // top-16 kept per row (compact-thread regs)
#define NCAP    64                  // buffer depth == max inserts per 64-col phase

#define RSB     208                 // bytes per fp8 row in smem (192 + 16 pad)
#define TILEB   (TM * RSB)          // 26624 bytes per B tile (padded, contiguous)

// ---------------------------------------------------------------------------
// Global scratch (no cudaMalloc allowed)
// ---------------------------------------------------------------------------
__device__ float   g_ynorm[NTRAIN];
__device__ uint8_t g_A8[NTEST * DIM];            // H_test  e4m3, row-major 192B rows
__device__ uint8_t g_B8[NTILES * TILEB];         // H_train e4m3, tile-padded layout

// ---------------------------------------------------------------------------
// PTX helpers (base ISA: sm_89/sm_90 features, legal on sm_100 without 'a')
// ---------------------------------------------------------------------------
__device__ __forceinline__ uint32_t smem_u32(const void* p) {
    uint32_t a;
    asm("{ .reg .u64 t; cvta.to.shared.u64 t, %1; cvt.u32.u64 %0, t; }"
        : "=r"(a) : "l"(p));
    return a;
}

#define CP_ASYNC16(dst, src) \
    asm volatile("cp.async.cg.shared.global [%0], [%1], 16;" :: "r"(dst), "l"(src))
#define CP_COMMIT() asm volatile("cp.async.commit_group;" ::: "memory")
#define CP_WAIT0()  asm volatile("cp.async.wait_group 0;" ::: "memory")

#define MBAR_INIT(mb, n) \
    asm volatile("mbarrier.init.shared.b64 [%0], %1;" :: "r"((uint32_t)(mb)), "r"((uint32_t)(n)) : "memory")
#define MBAR_EXPECT_TX(mb, bytes) \
    asm volatile("mbarrier.arrive.expect_tx.shared.b64 _, [%0], %1;" :: "r"((uint32_t)(mb)), "r"((uint32_t)(bytes)) : "memory")
#define CP_BULK(dst, src, sz, mb) \
    asm volatile("cp.async.bulk.shared::cluster.global.mbarrier::complete_tx::bytes [%0], [%1], %2, [%3];" \
                 :: "r"((uint32_t)(dst)), "l"(src), "r"((uint32_t)(sz)), "r"((uint32_t)(mb)) : "memory")
#define FENCE_PROXY_ASYNC() asm volatile("fence.proxy.async.shared::cta;" ::: "memory")

#define MBAR_WAIT(mb, par) do {                                                     \
    uint32_t _mb = (uint32_t)(mb); uint32_t _p = (uint32_t)(par); uint32_t _done;   \
    asm volatile("{ .reg .pred p; mbarrier.try_wait.parity.acquire.cta.shared::cta.b64 p, [%1], %2; selp.b32 %0, 1, 0, p; }" \
                 : "=r"(_done) : "r"(_mb), "r"(_p) : "memory");                     \
    if (!_done) {                                                                   \
        asm volatile("{ .reg .pred P1; WL_%=: mbarrier.try_wait.parity.acquire.cta.shared::cta.b64 P1, [%0], %1, 0x989680; @P1 bra.uni WD_%=; bra.uni WL_%=; WD_%=: }" \
                     :: "r"(_mb), "r"(_p) : "memory");                              \
    }                                                                               \
} while (0)

#define LDMATRIX_X4(r0, r1, r2, r3, addr) \
    asm volatile("ldmatrix.sync.aligned.m8n8.x4.shared.b16 {%0,%1,%2,%3}, [%4];" \
                 : "=r"(r0), "=r"(r1), "=r"(r2), "=r"(r3) : "r"(addr))

__device__ __forceinline__ void mma_fp8(float* c,
                                        uint32_t a0, uint32_t a1, uint32_t a2, uint32_t a3,
                                        uint32_t b0, uint32_t b1) {
    asm volatile("mma.sync.aligned.m16n8k32.row.col.f32.e4m3.e4m3.f32 "
                 "{%0,%1,%2,%3}, {%4,%5,%6,%7}, {%8,%9}, {%0,%1,%2,%3};"
                 : "+f"(c[0]), "+f"(c[1]), "+f"(c[2]), "+f"(c[3])
                 : "r"(a0), "r"(a1), "r"(a2), "r"(a3), "r"(b0), "r"(b1));
}

// ---------------------------------------------------------------------------
// SMEM layout (bytes)
// ---------------------------------------------------------------------------
#define OFF_B        0                       // double buffer: +0 / +TILEB
#define OFF_A        (2 * TILEB)             // 53248, single A buffer
#define OFF_YNS      (OFF_A + TILEB)         // 79872  float [128]
#define OFF_THR      (OFF_YNS + 512)         // 80384  float [128]
#define OFF_CNT      (OFF_THR + 512)         // 80896  int   [128]
#define OFF_BUFD     (OFF_CNT + 512)         // 81408  float [128][NCAP]
#define OFF_BUFI     (OFF_BUFD + 32768)      // 114176 int   [128][NCAP] / cand reuse
#define OFF_MBAR     (OFF_BUFI + 32768)      // 146944 two 8B mbarriers
#define SMEM_BYTES   (OFF_MBAR + 32)         // 146976

// ---------------------------------------------------------------------------
// Prep kernel: one warp per row index w (< NTRAIN):
//  - Htrain[w] -> e4m3 into tile-padded g_B8, squared norm -> g_ynorm[w]
//  - Htest[w]  -> e4m3 into row-major g_A8
// ---------------------------------------------------------------------------
__device__ __forceinline__ uint32_t pack4_e4m3(float f0, float f1, float f2, float f3) {
    uint32_t b0 = __nv_cvt_float_to_fp8(f0, __NV_SATFINITE, __NV_E4M3);
    uint32_t b1 = __nv_cvt_float_to_fp8(f1, __NV_SATFINITE, __NV_E4M3);
    uint32_t b2 = __nv_cvt_float_to_fp8(f2, __NV_SATFINITE, __NV_E4M3);
    uint32_t b3 = __nv_cvt_float_to_fp8(f3, __NV_SATFINITE, __NV_E4M3);
    return b0 | (b1 << 8) | (b2 << 16) | (b3 << 24);
}

__global__ void prep_kernel(const float* __restrict__ Htest,
                            const float* __restrict__ Htrain) {
    int w    = (blockIdx.x * blockDim.x + threadIdx.x) >> 5;
    int lane = threadIdx.x & 31;
    if (w >= NTRAIN) return;

    const float4* tr = (const float4*)(Htrain + (size_t)w * DIM);  // 48 float4
    const float4* te = (const float4*)(Htest  + (size_t)w * DIM);
    uint32_t* ob = (uint32_t*)(g_B8 + (size_t)(w >> 7) * TILEB + (size_t)(w & 127) * RSB);
    uint32_t* oa = (uint32_t*)(g_A8 + (size_t)w * DIM);

    float s = 0.f;
    #pragma unroll
    for (int j = 0; j < 2; j++) {
        int c = lane + 32 * j;
        if (c < 48) {
            float4 b = tr[c];
            float4 a = te[c];
            s = fmaf(b.x, b.x, s); s = fmaf(b.y, b.y, s);
            s = fmaf(b.z, b.z, s); s = fmaf(b.w, b.w, s);
            ob[c] = pack4_e4m3(b.x, b.y, b.z, b.w);
            oa[c] = pack4_e4m3(a.x, a.y, a.z, a.w);
        }
    }
    #pragma unroll
    for (int o = 16; o; o >>= 1) s += __shfl_xor_sync(0xffffffffu, s, o);
    if (lane == 0) g_ynorm[w] = s;
}

// ---------------------------------------------------------------------------
// Main kernel: fp8 mma.sync GEMM (bulk-copied B) -> top-16 -> exact fp32 re-rank
// ---------------------------------------------------------------------------
__global__ __launch_bounds__(NTHREADS, 1)
void knn_mma_kernel(const float* __restrict__ Htest,
                    const float* __restrict__ Htrain,
                    const float* __restrict__ phat,
                    float* __restrict__ out) {
    extern __shared__ __align__(1024) char smem[];
    const uint32_t sbase = smem_u32(smem);
    const int tid   = threadIdx.x;
    const int wid   = tid >> 5;
    const int lid   = tid & 31;
    const int warpM = wid & 3;       // 0..3 -> rows warpM*32..+31
    const int warpN = wid >> 2;      // 0..3 -> cols warpN*32..+31
    const int m0    = blockIdx.x * TM;

    float* yns  = (float*)(smem + OFF_YNS);
    float* thr  = (float*)(smem + OFF_THR);
    int*   cnt  = (int*)  (smem + OFF_CNT);
    float* bufd = (float*)(smem + OFF_BUFD);
    int*   bufi = (int*)  (smem + OFF_BUFI);
    const uint32_t mbar0 = sbase + OFF_MBAR;
    const uint32_t mbar1 = sbase + OFF_MBAR + 8;

    // ---- prologue ----
    if (tid == 0) { MBAR_INIT(mbar0, 1); MBAR_INIT(mbar1, 1); }
    FENCE_PROXY_ASYNC();
    __syncthreads();

    if (tid == 0) {
        MBAR_EXPECT_TX(mbar0, TILEB);
        CP_BULK(sbase + OFF_B, (const char*)g_B8, TILEB, mbar0);
    }

    // A tile: 128 rows x 12 chunks of 16B via cp.async (one-time)
    #pragma unroll
    for (int it = 0; it < (TM * 12) / NTHREADS; it++) {
        int g  = tid + it * NTHREADS;        // 0..1535
        int r  = g / 12;
        int ch = g % 12;
        CP_ASYNC16(sbase + OFF_A + r * RSB + ch * 16,
                   (const char*)g_A8 + (size_t)(m0 + r) * DIM + ch * 16);
    }
    CP_COMMIT();

    if (tid < TM) { thr[tid] = FLT_MAX; cnt[tid] = 0; }

    // private top-16 for the compact thread (row == tid, tid < 128)
    float pd[NCAND]; int pi[NCAND];
    #pragma unroll
    for (int i = 0; i < NCAND; i++) { pd[i] = FLT_MAX; pi[i] = -1; }

    CP_WAIT0();
    __syncthreads();

    const int lrow   = lid & 15;
    const int lchunk = lid >> 4;
    uint32_t a_addr[2];
    #pragma unroll
    for (int mf = 0; mf < 2; mf++)
        a_addr[mf] = sbase + OFF_A +
                     (warpM * 32 + mf * 16 + lrow) * RSB + lchunk * 16;

    const int erow0 = warpM * 32 + (lid >> 2);
    const int ecol0 = warpN * 32 + 2 * (lid & 3);

    // ---- main loop over B tiles ----
    for (int jt = 0; jt < NTILES; jt++) {
        const int cur = jt & 1;

        // issue next tile's bulk load (prev readers of buf[1-cur] are done:
        // they arrived at tile jt-1's final barrier before we got here)
        if (tid == 0 && jt + 1 < NTILES) {
            uint32_t mb = (1 - cur) ? mbar1 : mbar0;
            MBAR_EXPECT_TX(mb, TILEB);
            CP_BULK(sbase + OFF_B + (1 - cur) * TILEB,
                    (const char*)g_B8 + (size_t)(jt + 1) * TILEB, TILEB, mb);
        }
        if (tid < TM) yns[tid] = g_ynorm[jt * TN + tid];
        __syncthreads();                       // yns visible to all

        MBAR_WAIT(cur ? mbar1 : mbar0, (jt >> 1) & 1);   // tile jt data ready

        // ---- 128x128x192 fp8 mma: warp tile 32x32, K=32 per step ----
        float acc[2][4][4];
        #pragma unroll
        for (int mf = 0; mf < 2; mf++)
            #pragma unroll
            for (int nf = 0; nf < 4; nf++)
                #pragma unroll
                for (int q = 0; q < 4; q++) acc[mf][nf][q] = 0.f;

        uint32_t b_base = sbase + OFF_B + cur * TILEB +
                          (warpN * 32 + lrow) * RSB + lchunk * 16;

        #pragma unroll
        for (int ks = 0; ks < KSTEPS; ks++) {
            const uint32_t ka = ks * 32;       // 32 fp8 per kstep
            uint32_t a[2][4], b[2][4];
            LDMATRIX_X4(a[0][0], a[0][1], a[0][2], a[0][3], a_addr[0] + ka);
            LDMATRIX_X4(a[1][0], a[1][1], a[1][2], a[1][3], a_addr[1] + ka);
            LDMATRIX_X4(b[0][0], b[0][1], b[0][2], b[0][3], b_base + ka);
            LDMATRIX_X4(b[1][0], b[1][1], b[1][2], b[1][3],
                        b_base + 16 * RSB + ka);
            #pragma unroll
            for (int mf = 0; mf < 2; mf++)
                #pragma unroll
                for (int nf = 0; nf < 4; nf++)
                    mma_fp8(acc[mf][nf],
                            a[mf][0], a[mf][1], a[mf][2], a[mf][3],
                            b[nf >> 1][nf & 1], b[nf >> 1][2 + (nf & 1)]);
        }

        // ---- epilogue: 2 phases x 64 cols/row; inserts <= NCAP by construction ----
        const int colbase = jt * TN;
        #pragma unroll
        for (int ph = 0; ph < 2; ph++) {
            #pragma unroll
            for (int nfp = 0; nfp < 2; nfp++) {
                const int nf   = ph * 2 + nfp;
                const int col0 = ecol0 + nf * 8;
                const int col1 = col0 + 1;
                const float y0 = yns[col0];
                const float y1 = yns[col1];
                const int g0 = colbase + col0;
                const int g1 = colbase + col1;
                #pragma unroll
                for (int mf = 0; mf < 2; mf++) {
                    const float* cc = acc[mf][nf];
                    const int r0 = erow0 + mf * 16;
                    const int r1 = r0 + 8;
                    float d00 = fmaf(-2.f, cc[0], y0);
                    float d01 = fmaf(-2.f, cc[1], y1);
                    float d10 = fmaf(-2.f, cc[2], y0);
                    float d11 = fmaf(-2.f, cc[3], y1);
                    if (d00 < thr[r0]) {
                        int p = atomicAdd(&cnt[r0], 1);
                        bufd[r0*NCAP+p] = d00; bufi[r0*NCAP+p] = g0;
                    }
                    if (d01 < thr[r0]) {
                        int p = atomicAdd(&cnt[r0], 1);
                        bufd[r0*NCAP+p] = d01; bufi[r0*NCAP+p] = g1;
                    }
                    if (d10 < thr[r1]) {
                        int p = atomicAdd(&cnt[r1], 1);
                        bufd[r1*NCAP+p] = d10; bufi[r1*NCAP+p] = g0;
                    }
                    if (d11 < thr[r1]) {
                        int p = atomicAdd(&cnt[r1], 1);
                        bufd[r1*NCAP+p] = d11; bufi[r1*NCAP+p] = g1;
                    }
                }
            }
            __syncthreads();
            if (tid < TM) {
                int cn = cnt[tid];
                if (cn > 0) {
                    for (int i = 0; i < cn; i++) {
                        float d = bufd[tid * NCAP + i];
                        if (d < pd[NCAND - 1]) {
                            int idx = bufi[tid * NCAP + i];
                            int j = NCAND - 1;
                            while (j > 0 && pd[j - 1] > d) {
                                pd[j] = pd[j - 1]; pi[j] = pi[j - 1]; j--;
                            }
                            pd[j] = d; pi[j] = idx;
                        }
                    }
                    thr[tid] = pd[NCAND - 1];
                    cnt[tid] = 0;
                }
            }
            __syncthreads();
        }
    }

    // ---- dump candidates (reuse bufi region) ----
    int* cand = bufi;                          // [128][NCAND]
    if (tid < TM) {
        #pragma unroll
        for (int i = 0; i < NCAND; i++) cand[tid * NCAND + i] = pi[i];
    }
    __syncthreads();

    // ---- exact fp32 re-rank: warp per row, 16 candidates ----
    for (int r = wid; r < TM; r += 16) {
        const int rowg = m0 + r;
        const float* xrow = Htest + (size_t)rowg * DIM;
        float xv[6];
        #pragma unroll
        for (int j = 0; j < 6; j++) xv[j] = xrow[lid + 32 * j];

        float bd[KNN]; int bi[KNN];
        #pragma unroll
        for (int i = 0; i < KNN; i++) { bd[i] = FLT_MAX; bi[i] = 0x7fffffff; }

        for (int c = 0; c < NCAND; c++) {
            int idx = cand[r * NCAND + c];
            if (idx < 0) continue;
            const float* trow = Htrain + (size_t)idx * DIM;
            float s = 0.f;
            #pragma unroll
            for (int j = 0; j < 6; j++) s = fmaf(xv[j], trow[lid + 32 * j], s);
            #pragma unroll
            for (int o = 16; o; o >>= 1) s += __shfl_xor_sync(0xffffffffu, s, o);
            if (lid == 0) {
                float d = g_ynorm[idx] - 2.0f * s;
                int j = KNN;
                while (j > 0 && (d < bd[j - 1] ||
                                 (d == bd[j - 1] && idx < bi[j - 1]))) j--;
                if (j < KNN) {
                    for (int q = KNN - 1; q > j; q--) { bd[q] = bd[q-1]; bi[q] = bi[q-1]; }
                    bd[j] = d; bi[j] = idx;
                }
            }
        }
        if (lid == 0) {
            float s0 = 0.f, s1 = 0.f;
            #pragma unroll
            for (int i = 0; i < KNN; i++) {
                int idx = bi[i];
                s0 += phat[idx];
                s1 += phat[NTRAIN + idx];
            }
            out[rowg]         = s0 * (1.0f / KNN);
            out[NTEST + rowg] = s1 * (1.0f / KNN);
        }
    }
}

// ---------------------------------------------------------------------------
extern "C" void kernel_launch(void* const* d_in, const int* in_sizes, int n_in,
                              void* d_out, int out_size) {
    const float* Htest  = (const float*)d_in[0];
    const float* Htrain = (const float*)d_in[1];
    const float* phat   = (const float*)d_in[2];
    float* out = (float*)d_out;

    prep_kernel<<<(NTRAIN * 32) / 256, 256>>>(Htest, Htrain);

    cudaFuncSetAttribute(knn_mma_kernel,
                         cudaFuncAttributeMaxDynamicSharedMemorySize, SMEM_BYTES);
    knn_mma_kernel<<<NTEST / TM, NTHREADS, SMEM_BYTES>>>(Htest, Htrain, phat, out);
}